// round 16
// baseline (speedup 1.0000x reference)
#include <cuda_runtime.h>
#include <cuda_bf16.h>
#include <cuda_fp16.h>
#include <math.h>
#include <stdint.h>

// ---------------- problem constants ----------------
#define BATCH 8
#define SEQ   96
#define PRED  96
#define NVARS 862
#define NMARK 4
#define LTOK  866
#define TTOK  (BATCH*LTOK)   // 6928
#define DM    512
#define DS    16
#define DFF   512
#define RK    32
#define NL    2

// chunked scan: warp = 32 d-channels, 16 states/lane in registers
#define NCH   32
#define CHL   28
#define NWARP (2*BATCH*16*NCH)
#define NSTATE ((size_t)NWARP*32*16)

#define CDIV(a,b) (((a)+(b)-1)/(b))

// ---- half-weight buffer element counts ----
#define N_EMB (512*96)
#define N_INP (2*2*1024*512)
#define N_OUT (2*512*1024)          // concatenated: [l][n][1024]
#define N_F1  (2*512*512)
#define N_F2  (2*512*512)
#define N_GW  (512*512)
#define N_PW  (96*512)
#define N_WALL (N_EMB+N_INP+N_OUT+N_F1+N_F2+N_GW+N_PW)
#define N_WC  (4*544*512)

// ================= scratch (static; no allocs) =============================
constexpr size_t OFF_TOK  = 0;
constexpr size_t OFF_DEC  = OFF_TOK  + (size_t)TTOK*96;
constexpr size_t OFF_ENC  = OFF_DEC  + (size_t)TTOK*96;
constexpr size_t OFF_RAW  = OFF_ENC  + (size_t)TTOK*DM;
constexpr size_t OFF_XZB  = OFF_RAW  + (size_t)TTOK*DM;        // [T, 2048]
constexpr size_t OFF_XC0  = OFF_XZB  + (size_t)TTOK*4*DM;
constexpr size_t OFF_XC1  = OFF_XC0  + (size_t)TTOK*DM;
constexpr size_t OFF_DX   = OFF_XC1  + (size_t)TTOK*DM;        // [T,2048] (dlt,x)
constexpr size_t OFF_BC   = OFF_DX   + (size_t)TTOK*2048;      // [T,64] (B,C)
constexpr size_t OFF_YP   = OFF_BC   + (size_t)TTOK*64;        // [T,1024] yp0|yp1
constexpr size_t OFF_MO   = OFF_YP   + (size_t)TTOK*1024;      // [T,512]
constexpr size_t OFF_T1   = OFF_MO   + (size_t)TTOK*DM;
constexpr size_t OFF_T2   = OFF_T1   + (size_t)TTOK*DM;
constexpr size_t OFF_T3   = OFF_T2   + (size_t)TTOK*DM;
constexpr size_t OFF_WH   = OFF_T3   + (size_t)TTOK*DM;        // half weights
constexpr size_t OFF_WCH  = OFF_WH   + (N_WALL + 1) / 2;       // wcomb half
constexpr size_t OFF_MEAN = OFF_WCH  + (N_WC + 1) / 2;
constexpr size_t OFF_STD  = OFF_MEAN + (size_t)BATCH*NVARS;
constexpr size_t OFF_P    = OFF_STD  + (size_t)BATCH*NVARS;
constexpr size_t OFF_HL   = OFF_P    + NSTATE;
constexpr size_t OFF_HI   = OFF_HL   + NSTATE;
constexpr size_t SCRATCH_FLOATS = OFF_HI + NSTATE;

__device__ float g_scratch[SCRATCH_FLOATS];

// ================= tensor-core GEMM =========================================
// C[M,N] = act(A[M,K(lda)] * Wh[N,K]^T + bias)
enum { ACT_NONE = 0, ACT_RELU = 1, ACT_DELTABC = 2, ACT_GATE = 3, ACT_DUP = 4 };

#define BM 64
#define BN 128
#define LPITCH 36
#define ROWB 144
#define A_TILE_B (64*ROWB)
#define B_TILE_B (128*ROWB)
#define STAGE_B  (A_TILE_B + B_TILE_B)
#define SMEM_GEMM (2*STAGE_B)

__device__ __forceinline__ uint32_t smem_u32(const void* p) {
    uint32_t a;
    asm("{ .reg .u64 t; cvta.to.shared.u64 t, %1; cvt.u32.u64 %0, t; }"
        : "=r"(a) : "l"(p));
    return a;
}

__device__ __forceinline__ uint32_t pack_fp16(float a, float b) {
    __half2 t = __floats2half2_rn(a, b);
    return *reinterpret_cast<uint32_t*>(&t);
}

__device__ __forceinline__ void cp16(uint32_t dst, const void* src, uint32_t sz) {
    asm volatile("cp.async.ca.shared.global [%0], [%1], 16, %2;"
        :: "r"(dst), "l"(src), "r"(sz) : "memory");
}
#define CP_COMMIT() asm volatile("cp.async.commit_group;" ::: "memory")
#define CP_WAIT0()  asm volatile("cp.async.wait_group 0;" ::: "memory")

#define LDSM_X4(r0,r1,r2,r3,addr) \
    asm volatile("ldmatrix.sync.aligned.m8n8.x4.shared.b16 {%0,%1,%2,%3}, [%4];" \
        : "=r"(r0),"=r"(r1),"=r"(r2),"=r"(r3) : "r"(addr))

#define MMA_FP16(d,a,b0,b1) \
    asm volatile("mma.sync.aligned.m16n8k16.row.col.f32.f16.f16.f32 " \
        "{%0,%1,%2,%3}, {%4,%5,%6,%7}, {%8,%9}, {%0,%1,%2,%3};" \
        : "+f"((d)[0]),"+f"((d)[1]),"+f"((d)[2]),"+f"((d)[3]) \
        : "r"((a)[0]),"r"((a)[1]),"r"((a)[2]),"r"((a)[3]), "r"(b0),"r"(b1))

template <int ACT>
__global__ void __launch_bounds__(256, 4)
mma_gemm(const float* __restrict__ A, int lda,
         const __half* __restrict__ W,
         const float* __restrict__ bias,
         float* __restrict__ C, int ldc,
         int M, int N, int K,
         const float* __restrict__ e1, const float* __restrict__ e2,
         size_t zsA, size_t zsW, size_t zsC, size_t zsBias)
{
    extern __shared__ char smem[];
    const uint32_t sbase = smem_u32(smem);
    const int tid  = threadIdx.x;
    const int lane = tid & 31;
    const int wid  = tid >> 5;
    const int warp_m = wid & 1;
    const int warp_n = wid >> 1;
    const int bm = blockIdx.y * BM, bn = blockIdx.x * BN;

    A += blockIdx.z * zsA;
    W += blockIdx.z * zsW;
    C += blockIdx.z * zsC;
    if (bias) bias += blockIdx.z * zsBias;

    const int c4a = tid & 7;            // 16B chunk of A row (4 floats)
    const int r0a = tid >> 3;           // A base row (0..31)
    const int c4b = tid & 3;            // 16B chunk of B row (8 halves)
    const int r0b = tid >> 2;           // B base row (0..63)

    float4 aReg[2];

    auto load_A = [&](int kt) {
        const float* Ap = A + (size_t)kt * 32 + (size_t)c4a * 4;
#pragma unroll
        for (int i = 0; i < 2; i++) {
            int gr = bm + r0a + i * 32;
            aReg[i] = (gr < M) ? *reinterpret_cast<const float4*>(Ap + (size_t)gr * lda)
                               : make_float4(0.f, 0.f, 0.f, 0.f);
        }
    };

    auto issue_B = [&](int kt, int s) {
        uint32_t sb = sbase + s * STAGE_B + A_TILE_B;
#pragma unroll
        for (int i = 0; i < 2; i++) {
            int row = r0b + i * 64;
            int gn = bn + row;
            int gcl = (gn < N) ? gn : 0;
            cp16(sb + row * ROWB + c4b * 16,
                 W + (size_t)gcl * K + kt * 32 + c4b * 8,
                 (gn < N) ? 16u : 0u);
        }
    };

    auto store_A = [&](int s) {
        uint32_t* sa = reinterpret_cast<uint32_t*>(smem + s * STAGE_B);
#pragma unroll
        for (int i = 0; i < 2; i++) {
            int row = r0a + i * 32;
            float4 v = aReg[i];
            uint32_t* p = sa + row * LPITCH + c4a * 2;
            p[0] = pack_fp16(v.x, v.y);
            p[1] = pack_fp16(v.z, v.w);
        }
    };

    const uint32_t a_off = (uint32_t)(warp_m * 32 + (lane & 15)) * ROWB + ((lane >> 4) * 16);
    const uint32_t b_off = (uint32_t)(warp_n * 32 + ((lane >> 4) & 1) * 8 + (lane & 7)) * ROWB
                         + (((lane >> 3) & 1) * 16);

    float acc[2][4][4];
#pragma unroll
    for (int i = 0; i < 2; i++)
#pragma unroll
        for (int j = 0; j < 4; j++)
#pragma unroll
            for (int e = 0; e < 4; e++) acc[i][j][e] = 0.f;

    const int KT = K / 32;
    load_A(0);
    issue_B(0, 0);
    CP_COMMIT();
    store_A(0);
    CP_WAIT0();
    __syncthreads();

    for (int kt = 0; kt < KT; kt++) {
        if (kt + 1 < KT) {
            load_A(kt + 1);
            issue_B(kt + 1, (kt + 1) & 1);
            CP_COMMIT();
        }
        const uint32_t Ab = sbase + (kt & 1) * STAGE_B;
        const uint32_t Bb = Ab + A_TILE_B;
#pragma unroll
        for (int kk = 0; kk < 2; kk++) {
            const uint32_t ao = Ab + a_off + kk * 32;
            const uint32_t bo = Bb + b_off + kk * 32;
            uint32_t a[2][4];
#pragma unroll
            for (int mt = 0; mt < 2; mt++)
                LDSM_X4(a[mt][0], a[mt][1], a[mt][2], a[mt][3], ao + mt * 16 * ROWB);
            uint32_t b[2][4];
#pragma unroll
            for (int p = 0; p < 2; p++)
                LDSM_X4(b[p][0], b[p][1], b[p][2], b[p][3], bo + p * 16 * ROWB);
#pragma unroll
            for (int mt = 0; mt < 2; mt++) {
                MMA_FP16(acc[mt][0], a[mt], b[0][0], b[0][1]);
                MMA_FP16(acc[mt][1], a[mt], b[0][2], b[0][3]);
                MMA_FP16(acc[mt][2], a[mt], b[1][0], b[1][1]);
                MMA_FP16(acc[mt][3], a[mt], b[1][2], b[1][3]);
            }
        }
        if (kt + 1 < KT) store_A((kt + 1) & 1);
        CP_WAIT0();
        __syncthreads();
    }

    // ---- epilogue ----
    const int er = bm + warp_m * 32 + (lane >> 2);
    const int ec = bn + warp_n * 32 + (lane & 3) * 2;
#pragma unroll
    for (int mt = 0; mt < 2; mt++) {
#pragma unroll
        for (int nt = 0; nt < 4; nt++) {
            int gc = ec + nt * 8;
            if (gc >= N) continue;
            float b0 = 0.f, b1 = 0.f;
            if (bias) {
                if (ACT == ACT_DELTABC) {
                    if (gc < 512)     b0 = bias[gc];
                    if (gc + 1 < 512) b1 = bias[gc + 1];
                } else {
                    b0 = bias[gc]; b1 = bias[gc + 1];
                }
            }
#pragma unroll
            for (int h = 0; h < 2; h++) {
                int gr = er + mt * 16 + h * 8;
                if (gr >= M) continue;
                float v0 = acc[mt][nt][h * 2 + 0];
                float v1 = acc[mt][nt][h * 2 + 1];
                if (ACT == ACT_NONE) {
                    v0 += b0; v1 += b1;
                    *reinterpret_cast<float2*>(&C[(size_t)gr * ldc + gc]) =
                        make_float2(v0, v1);
                } else if (ACT == ACT_DUP) {
                    v0 += b0; v1 += b1;
                    float2 o = make_float2(v0, v1);
                    size_t ix = (size_t)gr * ldc + gc;
                    *reinterpret_cast<float2*>(&C[ix]) = o;
                    *reinterpret_cast<float2*>(const_cast<float*>(&e2[ix])) = o;
                } else if (ACT == ACT_RELU) {
                    v0 = fmaxf(v0 + b0, 0.f); v1 = fmaxf(v1 + b1, 0.f);
                    *reinterpret_cast<float2*>(&C[(size_t)gr * ldc + gc]) =
                        make_float2(v0, v1);
                } else if (ACT == ACT_DELTABC) {
                    float* bco = const_cast<float*>(e1) + blockIdx.z * 32;
                    if (gc < 512) {
                        v0 += b0; v1 += b1;
                        v0 = fmaxf(v0, 0.f) + log1pf(__expf(-fabsf(v0)));
                        v1 = fmaxf(v1, 0.f) + log1pf(__expf(-fabsf(v1)));
                        C[(size_t)gr * 2048 + 2 * gc]     = v0;
                        C[(size_t)gr * 2048 + 2 * gc + 2] = v1;
                    } else if (gc < 528) {
                        int s = gc - 512;
                        bco[(size_t)gr * 64 + 2 * s]     = v0;
                        bco[(size_t)gr * 64 + 2 * s + 2] = v1;
                    } else if (gc < 544) {
                        int s = gc - 528;
                        bco[(size_t)gr * 64 + 2 * s + 1] = v0;
                        bco[(size_t)gr * 64 + 2 * s + 3] = v1;
                    }
                } else if (ACT == ACT_GATE) {
                    size_t ix = (size_t)gr * ldc + gc;
                    float s0 = 1.f / (1.f + __expf(-(v0 + b0)));
                    float s1 = 1.f / (1.f + __expf(-(v1 + b1)));
                    v0 = e1[ix] + s0 * e2[ix];
                    v1 = e1[ix + 1] + s1 * e2[ix + 1];
                    *reinterpret_cast<float2*>(&C[ix]) = make_float2(v0, v1);
                }
            }
        }
    }
}

// ================= weight conversion (one launch, all matrices) ============
__global__ void wconv_kernel(const float* __restrict__ emb,
                             const float* __restrict__ inp,
                             const float* __restrict__ outw,
                             const float* __restrict__ f1,
                             const float* __restrict__ f2,
                             const float* __restrict__ gw,
                             const float* __restrict__ pw,
                             __half* __restrict__ dst)
{
    int idx = blockIdx.x * blockDim.x + threadIdx.x;
    if (idx >= N_WALL) return;
    int i = idx;
    float v;
    if (i < N_EMB) { v = emb[i]; }
    else { i -= N_EMB;
    if (i < N_INP) { v = inp[i]; }
    else { i -= N_INP;
    if (i < N_OUT) {
        int l = i / (512 * 1024);
        int r = i - l * 512 * 1024;
        int n = r >> 10;
        int k = r & 1023;
        int dir = k >> 9;
        v = outw[(((size_t)l * 2 + dir) * 512 + n) * 512 + (k & 511)];
    }
    else { i -= N_OUT;
    if (i < N_F1)  { v = f1[i]; }
    else { i -= N_F1;
    if (i < N_F2)  { v = f2[i]; }
    else { i -= N_F2;
    if (i < N_GW)  { v = gw[i]; }
    else { i -= N_GW; v = pw[i]; } } } } } }
    dst[idx] = __float2half_rn(v);
}

// ================= small kernels ==========================================
__global__ void stats_tok_kernel(const float* __restrict__ x_enc,
                                 const float* __restrict__ x_mark,
                                 float* __restrict__ means,
                                 float* __restrict__ stds,
                                 float* __restrict__ tok)
{
    int idx = blockIdx.x * blockDim.x + threadIdx.x;
    if (idx >= BATCH * LTOK) return;
    int b = idx / LTOK, v = idx - b * LTOK;
    float* trow = tok + (size_t)idx * SEQ;
    if (v < NVARS) {
        const float* src = x_enc + (size_t)b * SEQ * NVARS + v;
        float s = 0.f, sq = 0.f;
        for (int t = 0; t < SEQ; t++) {
            float val = src[(size_t)t * NVARS];
            s += val; sq += val * val;
        }
        float m = s * (1.f / SEQ);
        float var = sq * (1.f / SEQ) - m * m;
        float sd = sqrtf(var + 1e-5f);
        means[b * NVARS + v] = m;
        stds[b * NVARS + v] = sd;
        float inv = 1.f / sd;
        for (int t = 0; t < SEQ; t++)
            trow[t] = (src[(size_t)t * NVARS] - m) * inv;
    } else {
        const float* src = x_mark + (size_t)b * SEQ * NMARK + (v - NVARS);
        for (int t = 0; t < SEQ; t++)
            trow[t] = src[(size_t)t * NMARK];
    }
}

__global__ void wcomb_kernel(const float* __restrict__ dtw,
                             const float* __restrict__ xpw,
                             __half* __restrict__ wcomb)
{
    int idx = blockIdx.x * blockDim.x + threadIdx.x;
    if (idx >= 4 * 544 * 512) return;
    int w = idx / (544 * 512);
    int rem = idx - w * 544 * 512;
    int n = rem >> 9;
    int k = rem & 511;
    float v;
    if (n < 512) {
        const float* dr = dtw + ((size_t)w * 512 + n) * 32;
        const float* xr = xpw + (size_t)w * 64 * 512 + k;
        v = 0.f;
#pragma unroll
        for (int r = 0; r < 32; r++) v = fmaf(dr[r], xr[(size_t)r * 512], v);
    } else {
        v = xpw[(size_t)w * 64 * 512 + (size_t)(32 + n - 512) * 512 + k];
    }
    wcomb[idx] = __float2half_rn(v);
}

__global__ void conv_silu_kernel(const float* __restrict__ xzB,
                                 const float* __restrict__ cw,
                                 const float* __restrict__ cb,
                                 float* __restrict__ xc0, float* __restrict__ xc1,
                                 float* __restrict__ dx)
{
    int idx = blockIdx.x * blockDim.x + threadIdx.x;
    const int n = TTOK * 256;
    if (idx >= 2 * n) return;
    int dir = idx >= n;
    int r = idx - dir * n;
    int d2 = r & 255;
    int t = r >> 8;
    int d = 2 * d2;
    int b = t / LTOK, l = t - b * LTOK;
    const float* base = xzB + (size_t)dir * 1024;
    float2 cur = *reinterpret_cast<const float2*>(base + (size_t)t * 2048 + d);
    int ln = dir ? (l + 1) : (l - 1);
    float2 nbv = make_float2(0.f, 0.f);
    if (ln >= 0 && ln < LTOK)
        nbv = *reinterpret_cast<const float2*>(base + (size_t)(t + (dir ? 1 : -1)) * 2048 + d);
    float4 wv = *reinterpret_cast<const float4*>(cw + (size_t)dir * 1024 + 2 * d);
    float2 cbv = *reinterpret_cast<const float2*>(cb + (size_t)dir * 512 + d);
    float v0 = wv.x * nbv.x + wv.y * cur.x + cbv.x;
    float v1 = wv.z * nbv.y + wv.w * cur.y + cbv.y;
    float o0 = v0 / (1.f + __expf(-v0));
    float o1 = v1 / (1.f + __expf(-v1));
    *reinterpret_cast<float2*>((dir ? xc1 : xc0) + (size_t)t * 512 + d) =
        make_float2(o0, o1);
    dx[(size_t)t * 2048 + dir * 1024 + 2 * d + 1] = o0;
    dx[(size_t)t * 2048 + dir * 1024 + 2 * d + 3] = o1;
}

// ---------------- chunked selective scan -----------------------------------
__global__ void __launch_bounds__(256)
scan_p1(const float* __restrict__ dx, const float* __restrict__ bcb,
        const float* __restrict__ A_log_l,
        float* __restrict__ P, float* __restrict__ H)
{
    int w = blockIdx.x * 8 + (threadIdx.x >> 5);
    int lane = threadIdx.x & 31;
    int ch = w & 31;
    int dblk = (w >> 5) & 15;
    int b = (w >> 9) & 7;
    int dir = w >> 12;
    int d = dblk * 32 + lane;

    float a[DS];
    bool structured = true;
#pragma unroll
    for (int s = 0; s < DS; s++) {
        a[s] = -__expf(A_log_l[((size_t)dir * DM + d) * DS + s]) * 1.44269504f;
        structured = structured &&
            (fabsf(a[s] - a[0] * (s + 1)) <= 1e-4f * fabsf(a[0] * (s + 1)));
    }

    float h[DS], Pr[DS];
#pragma unroll
    for (int s = 0; s < DS; s++) { h[s] = 0.f; Pr[s] = 1.f; }

    int i0 = ch * CHL;
    int nn = LTOK - i0; if (nn > CHL) nn = CHL; if (nn < 0) nn = 0;
    int l0 = dir ? (LTOK - 1 - i0) : i0;
    long t0 = (long)b * LTOK + l0;
    long stp = dir ? -1 : 1;
    const float2* dxp = (const float2*)dx + t0 * 1024 + dir * 512 + d;
    const float2* bp  = (const float2*)bcb + t0 * 32 + dir * 16;
    long sdx = stp * 1024, sbc = stp * 32;

    if (structured) {
        const float a0 = a[0];
        for (int i = 0; i < nn; i++) {
            float2 dv = *dxp;
            float u = dv.x * dv.y;
            float q = exp2f(dv.x * a0);
            float dA = 1.f;
#pragma unroll
            for (int s = 0; s < DS; s++) {
                dA *= q;
                float2 bcv = bp[s];
                Pr[s] *= dA;
                h[s] = fmaf(dA, h[s], bcv.x * u);
            }
            dxp += sdx; bp += sbc;
        }
    } else {
        for (int i = 0; i < nn; i++) {
            float2 dv = *dxp;
            float u = dv.x * dv.y;
#pragma unroll
            for (int s = 0; s < DS; s++) {
                float2 bcv = bp[s];
                float dA = exp2f(dv.x * a[s]);
                Pr[s] *= dA;
                h[s] = fmaf(dA, h[s], bcv.x * u);
            }
            dxp += sdx; bp += sbc;
        }
    }
    float* Po = P + ((size_t)w * 32 + lane) * 16;
    float* Ho = H + ((size_t)w * 32 + lane) * 16;
#pragma unroll
    for (int s = 0; s < DS; s++) { Po[s] = Pr[s]; Ho[s] = h[s]; }
}

__global__ void scan_comb(const float* __restrict__ P,
                          const float* __restrict__ Hl,
                          float* __restrict__ Hin)
{
    int idx = blockIdx.x * blockDim.x + threadIdx.x;
    if (idx >= 2 * BATCH * DM * 16) return;
    int s = idx & 15;
    int lane = (idx >> 4) & 31;
    int dblk = (idx >> 9) & 15;
    int b = (idx >> 13) & 7;
    int dir = idx >> 16;
    size_t w0 = (size_t)dir * 4096 + (size_t)b * 512 + (size_t)dblk * 32;
    float h = 0.f;
#pragma unroll
    for (int ch = 0; ch < NCH; ch++) {
        size_t o = ((w0 + ch) * 32 + lane) * 16 + s;
        Hin[o] = h;
        h = P[o] * h + Hl[o];
    }
}

// Pass 2: outputs yp interleaved [T,1024] = [yp_fwd | yp_rev]
__global__ void __launch_bounds__(256)
scan_p2(const float* __restrict__ dx, const float* __restrict__ bcb,
        const float* __restrict__ xzB,
        const float* __restrict__ A_log_l,
        const float* __restrict__ Dp_l,
        const float* __restrict__ Hin,
        float* __restrict__ yp)
{
    int w = blockIdx.x * 8 + (threadIdx.x >> 5);
    int lane = threadIdx.x & 31;
    int ch = w & 31;
    int dblk = (w >> 5) & 15;
    int b = (w >> 9) & 7;
    int dir = w >> 12;
    int d = dblk * 32 + lane;

    float a[DS];
    bool structured = true;
#pragma unroll
    for (int s = 0; s < DS; s++) {
        a[s] = -__expf(A_log_l[((size_t)dir * DM + d) * DS + s]) * 1.44269504f;
        structured = structured &&
            (fabsf(a[s] - a[0] * (s + 1)) <= 1e-4f * fabsf(a[0] * (s + 1)));
    }
    float Dv = Dp_l[dir * DM + d];

    float h[DS];
    const float* Hi = Hin + ((size_t)w * 32 + lane) * 16;
#pragma unroll
    for (int s = 0; s < DS; s++) h[s] = Hi[s];

    int i0 = ch * CHL;
    int nn = LTOK - i0; if (nn > CHL) nn = CHL; if (nn < 0) nn = 0;
    int l0 = dir ? (LTOK - 1 - i0) : i0;
    long t0 = (long)b * LTOK + l0;
    long stp = dir ? -1 : 1;
    const float2* dxp = (const float2*)dx + t0 * 1024 + dir * 512 + d;
    const float2* bp  = (const float2*)bcb + t0 * 32 + dir * 16;
    const float*  zp  = xzB + t0 * 2048 + dir * 1024 + 512 + d;
    float* ypp = yp + t0 * 1024 + dir * 512 + d;
    long sdx = stp * 1024, sbc = stp * 32, sz = stp * 2048, sy = stp * 1024;

    if (structured) {
        const float a0 = a[0];
        for (int i = 0; i < nn; i++) {
            float2 dv = *dxp;
            float u = dv.x * dv.y;
            float q = exp2f(dv.x * a0);
            float dA = 1.f;
            float y0 = 0.f, y1 = 0.f, y2 = 0.f, y3 = 0.f;
#pragma unroll
            for (int s = 0; s < DS; s++) {
                dA *= q;
                float2 bcv = bp[s];
                h[s] = fmaf(dA, h[s], bcv.x * u);
                float t = h[s] * bcv.y;
                if ((s & 3) == 0) y0 += t;
                else if ((s & 3) == 1) y1 += t;
                else if ((s & 3) == 2) y2 += t;
                else y3 += t;
            }
            float y = (y0 + y1) + (y2 + y3);
            float z = *zp;
            float szl = z / (1.f + __expf(-z));
            *ypp = (y + Dv * dv.y) * szl;
            dxp += sdx; bp += sbc; zp += sz; ypp += sy;
        }
    } else {
        for (int i = 0; i < nn; i++) {
            float2 dv = *dxp;
            float u = dv.x * dv.y;
            float y0 = 0.f, y1 = 0.f, y2 = 0.f, y3 = 0.f;
#pragma unroll
            for (int s = 0; s < DS; s++) {
                float2 bcv = bp[s];
                float dA = exp2f(dv.x * a[s]);
                h[s] = fmaf(dA, h[s], bcv.x * u);
                float t = h[s] * bcv.y;
                if ((s & 3) == 0) y0 += t;
                else if ((s & 3) == 1) y1 += t;
                else if ((s & 3) == 2) y2 += t;
                else y3 += t;
            }
            float y = (y0 + y1) + (y2 + y3);
            float z = *zp;
            float szl = z / (1.f + __expf(-z));
            *ypp = (y + Dv * dv.y) * szl;
            dxp += sdx; bp += sbc; zp += sz; ypp += sy;
        }
    }
}

// LayerNorm, float2 lanes
__global__ void ln_kernel(const float* __restrict__ i1,
                          const float* __restrict__ i2,
                          const float* __restrict__ i3,
                          const float* __restrict__ g,
                          const float* __restrict__ bta,
                          float* __restrict__ out)
{
    int row = blockIdx.x * (blockDim.x >> 5) + (threadIdx.x >> 5);
    int lane = threadIdx.x & 31;
    if (row >= TTOK) return;
    const float2* p1 = reinterpret_cast<const float2*>(i1 + (size_t)row * DM);
    const float2* p2 = i2 ? reinterpret_cast<const float2*>(i2 + (size_t)row * DM) : nullptr;
    const float2* p3 = i3 ? reinterpret_cast<const float2*>(i3 + (size_t)row * DM) : nullptr;
    float2 vals[8];
    float s = 0.f, sq = 0.f;
#pragma unroll
    for (int i = 0; i < 8; i++) {
        int j = lane + i * 32;
        float2 v = p1[j];
        if (p2) { float2 w = p2[j]; v.x += w.x; v.y += w.y; }
        if (p3) { float2 w = p3[j]; v.x += w.x; v.y += w.y; }
        vals[i] = v;
        s += v.x + v.y; sq += v.x * v.x + v.y * v.y;
    }
#pragma unroll
    for (int o = 16; o; o >>= 1) {
        s  += __shfl_xor_sync(0xffffffffu, s, o);
        sq += __shfl_xor_sync(0xffffffffu, sq, o);
    }
    float m = s * (1.f / DM);
    float var = sq * (1.f / DM) - m * m;
    float r = rsqrtf(var + 1e-5f);
    const float2* gp = reinterpret_cast<const float2*>(g);
    const float2* bp = reinterpret_cast<const float2*>(bta);
    float2* op = reinterpret_cast<float2*>(out + (size_t)row * DM);
#pragma unroll
    for (int i = 0; i < 8; i++) {
        int j = lane + i * 32;
        float2 gv = gp[j], bv = bp[j];
        op[j] = make_float2((vals[i].x - m) * r * gv.x + bv.x,
                            (vals[i].y - m) * r * gv.y + bv.y);
    }
}

__global__ void out_kernel(const float* __restrict__ dec,
                           const float* __restrict__ means,
                           const float* __restrict__ stds,
                           float* __restrict__ out)
{
    int idx = blockIdx.x * blockDim.x + threadIdx.x;
    if (idx >= BATCH * PRED * NVARS) return;
    int b = idx / (PRED * NVARS);
    int rem = idx - b * (PRED * NVARS);
    int p = rem / NVARS;
    int n = rem - p * NVARS;
    float v = dec[((size_t)b * LTOK + n) * PRED + p];
    out[idx] = v * stds[b * NVARS + n] + means[b * NVARS + n];
}

// ================= host orchestration ======================================
template <int ACT>
static void launch_mma(const float* A, int lda, const __half* W, const float* bias,
                       float* C, int ldc, int M, int N, int K,
                       const float* e1 = nullptr, const float* e2 = nullptr,
                       int Z = 1, size_t zsA = 0, size_t zsW = 0,
                       size_t zsC = 0, size_t zsBias = 0)
{
    dim3 grid(CDIV(N, BN), CDIV(M, BM), Z);
    mma_gemm<ACT><<<grid, 256, SMEM_GEMM>>>(A, lda, W, bias, C, ldc,
                                            M, N, K, e1, e2,
                                            zsA, zsW, zsC, zsBias);
}

extern "C" void kernel_launch(void* const* d_in, const int* in_sizes, int n_in,
                              void* d_out, int out_size)
{
    const float* x_enc    = (const float*)d_in[0];
    const float* x_mark   = (const float*)d_in[1];
    const float* emb_w    = (const float*)d_in[4];
    const float* emb_b    = (const float*)d_in[5];
    const float* in_proj  = (const float*)d_in[6];
    const float* conv_w   = (const float*)d_in[7];
    const float* conv_b   = (const float*)d_in[8];
    const float* x_proj   = (const float*)d_in[9];
    const float* dt_w     = (const float*)d_in[10];
    const float* dt_b     = (const float*)d_in[11];
    const float* A_log    = (const float*)d_in[12];
    const float* D_param  = (const float*)d_in[13];
    const float* out_w    = (const float*)d_in[14];
    const float* ffn_w1   = (const float*)d_in[15];
    const float* ffn_b1   = (const float*)d_in[16];
    const float* ffn_w2   = (const float*)d_in[17];
    const float* ffn_b2   = (const float*)d_in[18];
    const float* ln1_g    = (const float*)d_in[19];
    const float* ln1_b    = (const float*)d_in[20];
    const float* ln2_g    = (const float*)d_in[21];
    const float* ln2_b    = (const float*)d_in[22];
    const float* fin_g    = (const float*)d_in[23];
    const float* fin_b    = (const float*)d_in[24];
    const float* gate_w   = (const float*)d_in[25];
    const float* gate_b   = (const float*)d_in[26];
    const float* proj_w   = (const float*)d_in[27];
    const float* proj_b   = (const float*)d_in[28];

    cudaFuncSetAttribute((const void*)mma_gemm<ACT_DUP>,
                         cudaFuncAttributeMaxDynamicSharedMemorySize, SMEM_GEMM);
    cudaFuncSetAttribute((const void*)mma_gemm<ACT_NONE>,
                         cudaFuncAttributeMaxDynamicSharedMemorySize, SMEM_GEMM);
    cudaFuncSetAttribute((const void*)mma_gemm<ACT_DELTABC>,
                         cudaFuncAttributeMaxDynamicSharedMemorySize, SMEM_GEMM);
    cudaFuncSetAttribute((const void*)mma_gemm<ACT_RELU>,
                         cudaFuncAttributeMaxDynamicSharedMemorySize, SMEM_GEMM);
    cudaFuncSetAttribute((const void*)mma_gemm<ACT_GATE>,
                         cudaFuncAttributeMaxDynamicSharedMemorySize, SMEM_GEMM);

    float* S = nullptr;
    cudaGetSymbolAddress((void**)&S, g_scratch);

    float* tok   = S + OFF_TOK;
    float* dec   = S + OFF_DEC;
    float* enc   = S + OFF_ENC;
    float* raw   = S + OFF_RAW;
    float* xzB   = S + OFF_XZB;
    float* xcb[2] = { S + OFF_XC0,  S + OFF_XC1 };
    float* dx    = S + OFF_DX;
    float* bcb   = S + OFF_BC;
    float* yp    = S + OFF_YP;
    float* mo    = S + OFF_MO;
    float* t1    = S + OFF_T1;
    float* t2    = S + OFF_T2;
    float* t3    = S + OFF_T3;
    __half* wh   = (__half*)(S + OFF_WH);
    __half* wch  = (__half*)(S + OFF_WCH);
    float* means = S + OFF_MEAN;
    float* stds  = S + OFF_STD;
    float* Pbuf  = S + OFF_P;
    float* Hlbuf = S + OFF_HL;
    float* Hibuf = S + OFF_HI;

    __half* emb_h  = wh;
    __half* inp_h  = emb_h + N_EMB;
    __half* out_h  = inp_h + N_INP;    // concatenated [l][512][1024]
    __half* f1_h   = out_h + N_OUT;
    __half* f2_h   = f1_h + N_F1;
    __half* gw_h   = f2_h + N_F2;
    __half* pw_h   = gw_h + N_GW;

    wconv_kernel<<<CDIV(N_WALL, 256), 256>>>(emb_w, in_proj, out_w, ffn_w1,
                                             ffn_w2, gate_w, proj_w, wh);
    wcomb_kernel<<<CDIV(N_WC, 256), 256>>>(dt_w, x_proj, wch);
    stats_tok_kernel<<<CDIV(BATCH * LTOK, 256), 256>>>(x_enc, x_mark,
                                                       means, stds, tok);

    // embedding GEMM -> enc (+ duplicate into raw)
    launch_mma<ACT_DUP>(tok, SEQ, emb_h, emb_b, enc, DM, TTOK, DM, SEQ,
                        nullptr, raw);

    for (int l = 0; l < NL; l++) {
        // merged fwd+rev in_proj: N=2048
        launch_mma<ACT_NONE>(enc, DM, inp_h + (size_t)l * 2 * 2 * DM * DM,
                             nullptr, xzB, 4 * DM, TTOK, 4 * DM, DM);
        conv_silu_kernel<<<CDIV(2 * TTOK * 256, 256), 256>>>(
            xzB, conv_w + (size_t)l * 2 * DM * 2, conv_b + (size_t)l * 2 * DM,
            xcb[0], xcb[1], dx);

        // fused delta(softplus)+B+C GEMM, both dirs (z=2)
        launch_mma<ACT_DELTABC>(xcb[0], DM, wch + (size_t)l * 2 * 544 * 512,
                                dt_b + (size_t)l * 2 * DM, dx, 2048,
                                TTOK, 544, DM, bcb, nullptr,
                                2, (size_t)TTOK * DM, (size_t)544 * 512,
                                1024, DM);

        // chunked scan (three-kernel structure — proven fastest)
        scan_p1<<<NWARP / 8, 256>>>(dx, bcb,
                                    A_log + (size_t)l * 2 * DM * DS,
                                    Pbuf, Hlbuf);
        scan_comb<<<CDIV(2 * BATCH * DM * 16, 256), 256>>>(Pbuf, Hlbuf, Hibuf);
        scan_p2<<<NWARP / 8, 256>>>(dx, bcb, xzB,
                                    A_log + (size_t)l * 2 * DM * DS,
                                    D_param + (size_t)l * 2 * DM,
                                    Hibuf, yp);

        // merged out projection: mo = yp_fwd@W0^T + yp_rev@W1^T (K=1024)
        launch_mma<ACT_NONE>(yp, 1024, out_h + (size_t)l * 512 * 1024,
                             nullptr, mo, DM, TTOK, DM, 1024);

        ln_kernel<<<CDIV(TTOK, 8), 256>>>(enc, mo, nullptr,
                                          ln1_g + l * DM, ln1_b + l * DM, t1);
        launch_mma<ACT_RELU>(t1, DM, f1_h + (size_t)l * DFF * DM,
                             ffn_b1 + l * DFF, t2, DFF, TTOK, DFF, DM);
        launch_mma<ACT_NONE>(t2, DFF, f2_h + (size_t)l * DM * DFF,
                             ffn_b2 + l * DM, t3, DM, TTOK, DM, DFF);
        ln_kernel<<<CDIV(TTOK, 8), 256>>>(t1, t3, nullptr,
                                          ln2_g + l * DM, ln2_b + l * DM, enc);
    }

    ln_kernel<<<CDIV(TTOK, 8), 256>>>(enc, nullptr, nullptr, fin_g, fin_b, t2);
    launch_mma<ACT_GATE>(raw, DM, gw_h, gate_b, t1, DM, TTOK, DM, DM,
                         t2, raw);
    launch_mma<ACT_NONE>(t1, DM, pw_h, proj_b, dec, PRED, TTOK, PRED, DM);
    out_kernel<<<CDIV(BATCH * PRED * NVARS, 256), 256>>>(dec, means, stds,
                                                         (float*)d_out);
}

// round 17
// speedup vs baseline: 1.0732x; 1.0732x over previous
#include <cuda_runtime.h>
#include <cuda_bf16.h>
#include <cuda_fp16.h>
#include <math.h>
#include <stdint.h>

// ---------------- problem constants ----------------
#define BATCH 8
#define SEQ   96
#define PRED  96
#define NVARS 862
#define NMARK 4
#define LTOK  866
#define TTOK  (BATCH*LTOK)   // 6928
#define DM    512
#define DS    16
#define DFF   512
#define RK    32
#define NL    2

// chunked scan: warp = 32 d-channels, 16 states/lane in registers
#define NCH   32
#define CHL   28
#define NWARP (2*BATCH*16*NCH)
#define NSTATE ((size_t)NWARP*32*16)

#define CDIV(a,b) (((a)+(b)-1)/(b))

// ---- half-weight buffer element counts ----
#define N_EMB (512*96)
#define N_INP (2*2*1024*512)
#define N_OUT (2*512*1024)          // concatenated: [l][n][1024]
#define N_F1  (2*512*512)
#define N_F2  (2*512*512)
#define N_GW  (512*512)
#define N_PW  (96*512)
#define N_WALL (N_EMB+N_INP+N_OUT+N_F1+N_F2+N_GW+N_PW)
#define N_WC  (4*544*512)

// ================= scratch (static; no allocs) =============================
constexpr size_t OFF_TOK  = 0;
constexpr size_t OFF_DEC  = OFF_TOK  + (size_t)TTOK*96;
constexpr size_t OFF_ENC  = OFF_DEC  + (size_t)TTOK*96;
constexpr size_t OFF_RAW  = OFF_ENC  + (size_t)TTOK*DM;
constexpr size_t OFF_XZB  = OFF_RAW  + (size_t)TTOK*DM;        // [T, 2048]
constexpr size_t OFF_XC0  = OFF_XZB  + (size_t)TTOK*4*DM;
constexpr size_t OFF_XC1  = OFF_XC0  + (size_t)TTOK*DM;
constexpr size_t OFF_DX   = OFF_XC1  + (size_t)TTOK*DM;        // [T,2048] (dlt,x)
constexpr size_t OFF_BC   = OFF_DX   + (size_t)TTOK*2048;      // [T,64] (B,C)
constexpr size_t OFF_YP   = OFF_BC   + (size_t)TTOK*64;        // [T,1024] yp0|yp1
constexpr size_t OFF_MO   = OFF_YP   + (size_t)TTOK*1024;      // [T,512]
constexpr size_t OFF_T1   = OFF_MO   + (size_t)TTOK*DM;
constexpr size_t OFF_T2   = OFF_T1   + (size_t)TTOK*DM;
constexpr size_t OFF_T3   = OFF_T2   + (size_t)TTOK*DM;
constexpr size_t OFF_WH   = OFF_T3   + (size_t)TTOK*DM;        // half weights
constexpr size_t OFF_WCH  = OFF_WH   + (N_WALL + 1) / 2;       // wcomb half
constexpr size_t OFF_MEAN = OFF_WCH  + (N_WC + 1) / 2;
constexpr size_t OFF_STD  = OFF_MEAN + (size_t)BATCH*NVARS;
constexpr size_t OFF_P    = OFF_STD  + (size_t)BATCH*NVARS;
constexpr size_t OFF_HL   = OFF_P    + NSTATE;
constexpr size_t OFF_HI   = OFF_HL   + NSTATE;
constexpr size_t SCRATCH_FLOATS = OFF_HI + NSTATE;

__device__ float g_scratch[SCRATCH_FLOATS];

// ================= tensor-core GEMM =========================================
// C[M,N] = act(A[M,K(lda)] * Wh[N,K]^T + bias)
enum { ACT_NONE = 0, ACT_RELU = 1, ACT_DELTABC = 2, ACT_GATE = 3, ACT_DUP = 4,
       ACT_FINAL = 5 };

#define BM 64
#define BN 128
#define LPITCH 36
#define ROWB 144
#define A_TILE_B (64*ROWB)
#define B_TILE_B (128*ROWB)
#define STAGE_B  (A_TILE_B + B_TILE_B)
#define SMEM_GEMM (2*STAGE_B)

__device__ __forceinline__ uint32_t smem_u32(const void* p) {
    uint32_t a;
    asm("{ .reg .u64 t; cvta.to.shared.u64 t, %1; cvt.u32.u64 %0, t; }"
        : "=r"(a) : "l"(p));
    return a;
}

__device__ __forceinline__ uint32_t pack_fp16(float a, float b) {
    __half2 t = __floats2half2_rn(a, b);
    return *reinterpret_cast<uint32_t*>(&t);
}

#define LDSM_X4(r0,r1,r2,r3,addr) \
    asm volatile("ldmatrix.sync.aligned.m8n8.x4.shared.b16 {%0,%1,%2,%3}, [%4];" \
        : "=r"(r0),"=r"(r1),"=r"(r2),"=r"(r3) : "r"(addr))

#define MMA_FP16(d,a,b0,b1) \
    asm volatile("mma.sync.aligned.m16n8k16.row.col.f32.f16.f16.f32 " \
        "{%0,%1,%2,%3}, {%4,%5,%6,%7}, {%8,%9}, {%0,%1,%2,%3};" \
        : "+f"((d)[0]),"+f"((d)[1]),"+f"((d)[2]),"+f"((d)[3]) \
        : "r"((a)[0]),"r"((a)[1]),"r"((a)[2]),"r"((a)[3]), "r"(b0),"r"(b1))

template <int ACT>
__global__ void __launch_bounds__(256, 3)
mma_gemm(const float* __restrict__ A, int lda,
         const __half* __restrict__ W,
         const float* __restrict__ bias,
         float* __restrict__ C, int ldc,
         int M, int N, int K,
         const float* __restrict__ e1, const float* __restrict__ e2,
         size_t zsA, size_t zsW, size_t zsC, size_t zsBias)
{
    extern __shared__ char smem[];
    const uint32_t sbase = smem_u32(smem);
    const int tid  = threadIdx.x;
    const int lane = tid & 31;
    const int wid  = tid >> 5;
    const int warp_m = wid & 1;
    const int warp_n = wid >> 1;
    const int bm = blockIdx.y * BM, bn = blockIdx.x * BN;

    A += blockIdx.z * zsA;
    W += blockIdx.z * zsW;
    C += blockIdx.z * zsC;
    if (bias) bias += blockIdx.z * zsBias;

    const int c4 = tid & 7;
    const int r0g = tid >> 3;

    float4 aReg[2];
    uint2  bReg[4];

    auto load_global = [&](int kt) {
        const float*  Ap = A + (size_t)kt * 32 + (size_t)c4 * 4;
        const __half* Wp = W + (size_t)kt * 32 + (size_t)c4 * 4;
#pragma unroll
        for (int i = 0; i < 2; i++) {
            int gr = bm + r0g + i * 32;
            aReg[i] = (gr < M) ? *reinterpret_cast<const float4*>(Ap + (size_t)gr * lda)
                               : make_float4(0.f, 0.f, 0.f, 0.f);
        }
#pragma unroll
        for (int i = 0; i < 4; i++) {
            int gn = bn + r0g + i * 32;
            bReg[i] = (gn < N) ? *reinterpret_cast<const uint2*>(Wp + (size_t)gn * K)
                               : make_uint2(0u, 0u);
        }
    };

    auto store_stage = [&](int s) {
        uint32_t* sa = reinterpret_cast<uint32_t*>(smem + s * STAGE_B);
        uint32_t* sb = reinterpret_cast<uint32_t*>(smem + s * STAGE_B + A_TILE_B);
#pragma unroll
        for (int i = 0; i < 2; i++) {
            int row = r0g + i * 32;
            float4 v = aReg[i];
            uint32_t* p = sa + row * LPITCH + c4 * 2;
            p[0] = pack_fp16(v.x, v.y);
            p[1] = pack_fp16(v.z, v.w);
        }
#pragma unroll
        for (int i = 0; i < 4; i++) {
            int row = r0g + i * 32;
            uint32_t* p = sb + row * LPITCH + c4 * 2;
            p[0] = bReg[i].x;
            p[1] = bReg[i].y;
        }
    };

    const uint32_t a_off = (uint32_t)(warp_m * 32 + (lane & 15)) * ROWB + ((lane >> 4) * 16);
    const uint32_t b_off = (uint32_t)(warp_n * 32 + ((lane >> 4) & 1) * 8 + (lane & 7)) * ROWB
                         + (((lane >> 3) & 1) * 16);

    float acc[2][4][4];
#pragma unroll
    for (int i = 0; i < 2; i++)
#pragma unroll
        for (int j = 0; j < 4; j++)
#pragma unroll
            for (int e = 0; e < 4; e++) acc[i][j][e] = 0.f;

    const int KT = K / 32;
    load_global(0);
    store_stage(0);
    __syncthreads();

    for (int kt = 0; kt < KT; kt++) {
        if (kt + 1 < KT) load_global(kt + 1);
        const uint32_t Ab = sbase + (kt & 1) * STAGE_B;
        const uint32_t Bb = Ab + A_TILE_B;
#pragma unroll
        for (int kk = 0; kk < 2; kk++) {
            const uint32_t ao = Ab + a_off + kk * 32;
            const uint32_t bo = Bb + b_off + kk * 32;
            uint32_t a[2][4];
#pragma unroll
            for (int mt = 0; mt < 2; mt++)
                LDSM_X4(a[mt][0], a[mt][1], a[mt][2], a[mt][3], ao + mt * 16 * ROWB);
            uint32_t b[2][4];
#pragma unroll
            for (int p = 0; p < 2; p++)
                LDSM_X4(b[p][0], b[p][1], b[p][2], b[p][3], bo + p * 16 * ROWB);
#pragma unroll
            for (int mt = 0; mt < 2; mt++) {
                MMA_FP16(acc[mt][0], a[mt], b[0][0], b[0][1]);
                MMA_FP16(acc[mt][1], a[mt], b[0][2], b[0][3]);
                MMA_FP16(acc[mt][2], a[mt], b[1][0], b[1][1]);
                MMA_FP16(acc[mt][3], a[mt], b[1][2], b[1][3]);
            }
        }
        if (kt + 1 < KT) store_stage((kt + 1) & 1);
        __syncthreads();
    }

    // ---- epilogue ----
    const int er = bm + warp_m * 32 + (lane >> 2);
    const int ec = bn + warp_n * 32 + (lane & 3) * 2;
#pragma unroll
    for (int mt = 0; mt < 2; mt++) {
#pragma unroll
        for (int nt = 0; nt < 4; nt++) {
            int gc = ec + nt * 8;
            if (gc >= N) continue;
            float b0 = 0.f, b1 = 0.f;
            if (bias) {
                if (ACT == ACT_DELTABC) {
                    if (gc < 512)     b0 = bias[gc];
                    if (gc + 1 < 512) b1 = bias[gc + 1];
                } else {
                    b0 = bias[gc]; b1 = bias[gc + 1];
                }
            }
#pragma unroll
            for (int h = 0; h < 2; h++) {
                int gr = er + mt * 16 + h * 8;
                if (gr >= M) continue;
                float v0 = acc[mt][nt][h * 2 + 0];
                float v1 = acc[mt][nt][h * 2 + 1];
                if (ACT == ACT_NONE) {
                    v0 += b0; v1 += b1;
                    *reinterpret_cast<float2*>(&C[(size_t)gr * ldc + gc]) =
                        make_float2(v0, v1);
                } else if (ACT == ACT_DUP) {
                    v0 += b0; v1 += b1;
                    float2 o = make_float2(v0, v1);
                    size_t ix = (size_t)gr * ldc + gc;
                    *reinterpret_cast<float2*>(&C[ix]) = o;
                    *reinterpret_cast<float2*>(const_cast<float*>(&e2[ix])) = o;
                } else if (ACT == ACT_RELU) {
                    v0 = fmaxf(v0 + b0, 0.f); v1 = fmaxf(v1 + b1, 0.f);
                    *reinterpret_cast<float2*>(&C[(size_t)gr * ldc + gc]) =
                        make_float2(v0, v1);
                } else if (ACT == ACT_DELTABC) {
                    float* bco = const_cast<float*>(e1) + blockIdx.z * 32;
                    if (gc < 512) {
                        v0 += b0; v1 += b1;
                        v0 = fmaxf(v0, 0.f) + log1pf(__expf(-fabsf(v0)));
                        v1 = fmaxf(v1, 0.f) + log1pf(__expf(-fabsf(v1)));
                        C[(size_t)gr * 2048 + 2 * gc]     = v0;
                        C[(size_t)gr * 2048 + 2 * gc + 2] = v1;
                    } else if (gc < 528) {
                        int s = gc - 512;
                        bco[(size_t)gr * 64 + 2 * s]     = v0;
                        bco[(size_t)gr * 64 + 2 * s + 2] = v1;
                    } else if (gc < 544) {
                        int s = gc - 528;
                        bco[(size_t)gr * 64 + 2 * s + 1] = v0;
                        bco[(size_t)gr * 64 + 2 * s + 3] = v1;
                    }
                } else if (ACT == ACT_GATE) {
                    size_t ix = (size_t)gr * ldc + gc;
                    float s0 = 1.f / (1.f + __expf(-(v0 + b0)));
                    float s1 = 1.f / (1.f + __expf(-(v1 + b1)));
                    v0 = e1[ix] + s0 * e2[ix];
                    v1 = e1[ix + 1] + s1 * e2[ix + 1];
                    *reinterpret_cast<float2*>(&C[ix]) = make_float2(v0, v1);
                } else if (ACT == ACT_FINAL) {
                    // C = out[B][PRED][NVARS]; e1 = means, e2 = stds
                    int bb = gr / LTOK;
                    int n = gr - bb * LTOK;
                    if (n < NVARS) {
                        float sd = e2[bb * NVARS + n];
                        float mn = e1[bb * NVARS + n];
                        C[((size_t)bb * PRED + gc) * NVARS + n] =
                            (v0 + b0) * sd + mn;
                        if (gc + 1 < PRED)
                            C[((size_t)bb * PRED + gc + 1) * NVARS + n] =
                                (v1 + b1) * sd + mn;
                    }
                }
            }
        }
    }
}

// ================= weight conversion (one launch, all matrices) ============
__global__ void wconv_kernel(const float* __restrict__ emb,
                             const float* __restrict__ inp,
                             const float* __restrict__ outw,
                             const float* __restrict__ f1,
                             const float* __restrict__ f2,
                             const float* __restrict__ gw,
                             const float* __restrict__ pw,
                             __half* __restrict__ dst)
{
    int idx = blockIdx.x * blockDim.x + threadIdx.x;
    if (idx >= N_WALL) return;
    int i = idx;
    float v;
    if (i < N_EMB) { v = emb[i]; }
    else { i -= N_EMB;
    if (i < N_INP) { v = inp[i]; }
    else { i -= N_INP;
    if (i < N_OUT) {
        int l = i / (512 * 1024);
        int r = i - l * 512 * 1024;
        int n = r >> 10;
        int k = r & 1023;
        int dir = k >> 9;
        v = outw[(((size_t)l * 2 + dir) * 512 + n) * 512 + (k & 511)];
    }
    else { i -= N_OUT;
    if (i < N_F1)  { v = f1[i]; }
    else { i -= N_F1;
    if (i < N_F2)  { v = f2[i]; }
    else { i -= N_F2;
    if (i < N_GW)  { v = gw[i]; }
    else { i -= N_GW; v = pw[i]; } } } } } }
    dst[idx] = __float2half_rn(v);
}

// ================= small kernels ==========================================
__global__ void stats_tok_kernel(const float* __restrict__ x_enc,
                                 const float* __restrict__ x_mark,
                                 float* __restrict__ means,
                                 float* __restrict__ stds,
                                 float* __restrict__ tok)
{
    int idx = blockIdx.x * blockDim.x + threadIdx.x;
    if (idx >= BATCH * LTOK) return;
    int b = idx / LTOK, v = idx - b * LTOK;
    float* trow = tok + (size_t)idx * SEQ;
    if (v < NVARS) {
        const float* src = x_enc + (size_t)b * SEQ * NVARS + v;
        float s = 0.f, sq = 0.f;
        for (int t = 0; t < SEQ; t++) {
            float val = src[(size_t)t * NVARS];
            s += val; sq += val * val;
        }
        float m = s * (1.f / SEQ);
        float var = sq * (1.f / SEQ) - m * m;
        float sd = sqrtf(var + 1e-5f);
        means[b * NVARS + v] = m;
        stds[b * NVARS + v] = sd;
        float inv = 1.f / sd;
        for (int t = 0; t < SEQ; t++)
            trow[t] = (src[(size_t)t * NVARS] - m) * inv;
    } else {
        const float* src = x_mark + (size_t)b * SEQ * NMARK + (v - NVARS);
        for (int t = 0; t < SEQ; t++)
            trow[t] = src[(size_t)t * NMARK];
    }
}

__global__ void wcomb_kernel(const float* __restrict__ dtw,
                             const float* __restrict__ xpw,
                             __half* __restrict__ wcomb)
{
    int idx = blockIdx.x * blockDim.x + threadIdx.x;
    if (idx >= 4 * 544 * 512) return;
    int w = idx / (544 * 512);
    int rem = idx - w * 544 * 512;
    int n = rem >> 9;
    int k = rem & 511;
    float v;
    if (n < 512) {
        const float* dr = dtw + ((size_t)w * 512 + n) * 32;
        const float* xr = xpw + (size_t)w * 64 * 512 + k;
        v = 0.f;
#pragma unroll
        for (int r = 0; r < 32; r++) v = fmaf(dr[r], xr[(size_t)r * 512], v);
    } else {
        v = xpw[(size_t)w * 64 * 512 + (size_t)(32 + n - 512) * 512 + k];
    }
    wcomb[idx] = __float2half_rn(v);
}

__global__ void conv_silu_kernel(const float* __restrict__ xzB,
                                 const float* __restrict__ cw,
                                 const float* __restrict__ cb,
                                 float* __restrict__ xc0, float* __restrict__ xc1,
                                 float* __restrict__ dx)
{
    int idx = blockIdx.x * blockDim.x + threadIdx.x;
    const int n = TTOK * 256;
    if (idx >= 2 * n) return;
    int dir = idx >= n;
    int r = idx - dir * n;
    int d2 = r & 255;
    int t = r >> 8;
    int d = 2 * d2;
    int b = t / LTOK, l = t - b * LTOK;
    const float* base = xzB + (size_t)dir * 1024;
    float2 cur = *reinterpret_cast<const float2*>(base + (size_t)t * 2048 + d);
    int ln = dir ? (l + 1) : (l - 1);
    float2 nbv = make_float2(0.f, 0.f);
    if (ln >= 0 && ln < LTOK)
        nbv = *reinterpret_cast<const float2*>(base + (size_t)(t + (dir ? 1 : -1)) * 2048 + d);
    float4 wv = *reinterpret_cast<const float4*>(cw + (size_t)dir * 1024 + 2 * d);
    float2 cbv = *reinterpret_cast<const float2*>(cb + (size_t)dir * 512 + d);
    float v0 = wv.x * nbv.x + wv.y * cur.x + cbv.x;
    float v1 = wv.z * nbv.y + wv.w * cur.y + cbv.y;
    float o0 = v0 / (1.f + __expf(-v0));
    float o1 = v1 / (1.f + __expf(-v1));
    *reinterpret_cast<float2*>((dir ? xc1 : xc0) + (size_t)t * 512 + d) =
        make_float2(o0, o1);
    dx[(size_t)t * 2048 + dir * 1024 + 2 * d + 1] = o0;
    dx[(size_t)t * 2048 + dir * 1024 + 2 * d + 3] = o1;
}

// ---------------- chunked selective scan -----------------------------------
__global__ void __launch_bounds__(256)
scan_p1(const float* __restrict__ dx, const float* __restrict__ bcb,
        const float* __restrict__ A_log_l,
        float* __restrict__ P, float* __restrict__ H)
{
    int w = blockIdx.x * 8 + (threadIdx.x >> 5);
    int lane = threadIdx.x & 31;
    int ch = w & 31;
    int dblk = (w >> 5) & 15;
    int b = (w >> 9) & 7;
    int dir = w >> 12;
    int d = dblk * 32 + lane;

    float a[DS];
    bool structured = true;
#pragma unroll
    for (int s = 0; s < DS; s++) {
        a[s] = -__expf(A_log_l[((size_t)dir * DM + d) * DS + s]) * 1.44269504f;
        structured = structured &&
            (fabsf(a[s] - a[0] * (s + 1)) <= 1e-4f * fabsf(a[0] * (s + 1)));
    }

    float h[DS], Pr[DS];
#pragma unroll
    for (int s = 0; s < DS; s++) { h[s] = 0.f; Pr[s] = 1.f; }

    int i0 = ch * CHL;
    int nn = LTOK - i0; if (nn > CHL) nn = CHL; if (nn < 0) nn = 0;
    int l0 = dir ? (LTOK - 1 - i0) : i0;
    long t0 = (long)b * LTOK + l0;
    long stp = dir ? -1 : 1;
    const float2* dxp = (const float2*)dx + t0 * 1024 + dir * 512 + d;
    const float2* bp  = (const float2*)bcb + t0 * 32 + dir * 16;
    long sdx = stp * 1024, sbc = stp * 32;

    if (structured) {
        const float a0 = a[0];
        for (int i = 0; i < nn; i++) {
            float2 dv = *dxp;
            float u = dv.x * dv.y;
            float q = exp2f(dv.x * a0);
            float dA = 1.f;
#pragma unroll
            for (int s = 0; s < DS; s++) {
                dA *= q;
                float2 bcv = bp[s];
                Pr[s] *= dA;
                h[s] = fmaf(dA, h[s], bcv.x * u);
            }
            dxp += sdx; bp += sbc;
        }
    } else {
        for (int i = 0; i < nn; i++) {
            float2 dv = *dxp;
            float u = dv.x * dv.y;
#pragma unroll
            for (int s = 0; s < DS; s++) {
                float2 bcv = bp[s];
                float dA = exp2f(dv.x * a[s]);
                Pr[s] *= dA;
                h[s] = fmaf(dA, h[s], bcv.x * u);
            }
            dxp += sdx; bp += sbc;
        }
    }
    float* Po = P + ((size_t)w * 32 + lane) * 16;
    float* Ho = H + ((size_t)w * 32 + lane) * 16;
#pragma unroll
    for (int s = 0; s < DS; s++) { Po[s] = Pr[s]; Ho[s] = h[s]; }
}

__global__ void scan_comb(const float* __restrict__ P,
                          const float* __restrict__ Hl,
                          float* __restrict__ Hin)
{
    int idx = blockIdx.x * blockDim.x + threadIdx.x;
    if (idx >= 2 * BATCH * DM * 16) return;
    int s = idx & 15;
    int lane = (idx >> 4) & 31;
    int dblk = (idx >> 9) & 15;
    int b = (idx >> 13) & 7;
    int dir = idx >> 16;
    size_t w0 = (size_t)dir * 4096 + (size_t)b * 512 + (size_t)dblk * 32;
    float h = 0.f;
#pragma unroll
    for (int ch = 0; ch < NCH; ch++) {
        size_t o = ((w0 + ch) * 32 + lane) * 16 + s;
        Hin[o] = h;
        h = P[o] * h + Hl[o];
    }
}

// Pass 2: outputs yp interleaved [T,1024] = [yp_fwd | yp_rev]
__global__ void __launch_bounds__(256)
scan_p2(const float* __restrict__ dx, const float* __restrict__ bcb,
        const float* __restrict__ xzB,
        const float* __restrict__ A_log_l,
        const float* __restrict__ Dp_l,
        const float* __restrict__ Hin,
        float* __restrict__ yp)
{
    int w = blockIdx.x * 8 + (threadIdx.x >> 5);
    int lane = threadIdx.x & 31;
    int ch = w & 31;
    int dblk = (w >> 5) & 15;
    int b = (w >> 9) & 7;
    int dir = w >> 12;
    int d = dblk * 32 + lane;

    float a[DS];
    bool structured = true;
#pragma unroll
    for (int s = 0; s < DS; s++) {
        a[s] = -__expf(A_log_l[((size_t)dir * DM + d) * DS + s]) * 1.44269504f;
        structured = structured &&
            (fabsf(a[s] - a[0] * (s + 1)) <= 1e-4f * fabsf(a[0] * (s + 1)));
    }
    float Dv = Dp_l[dir * DM + d];

    float h[DS];
    const float* Hi = Hin + ((size_t)w * 32 + lane) * 16;
#pragma unroll
    for (int s = 0; s < DS; s++) h[s] = Hi[s];

    int i0 = ch * CHL;
    int nn = LTOK - i0; if (nn > CHL) nn = CHL; if (nn < 0) nn = 0;
    int l0 = dir ? (LTOK - 1 - i0) : i0;
    long t0 = (long)b * LTOK + l0;
    long stp = dir ? -1 : 1;
    const float2* dxp = (const float2*)dx + t0 * 1024 + dir * 512 + d;
    const float2* bp  = (const float2*)bcb + t0 * 32 + dir * 16;
    const float*  zp  = xzB + t0 * 2048 + dir * 1024 + 512 + d;
    float* ypp = yp + t0 * 1024 + dir * 512 + d;
    long sdx = stp * 1024, sbc = stp * 32, sz = stp * 2048, sy = stp * 1024;

    if (structured) {
        const float a0 = a[0];
        for (int i = 0; i < nn; i++) {
            float2 dv = *dxp;
            float u = dv.x * dv.y;
            float q = exp2f(dv.x * a0);
            float dA = 1.f;
            float y0 = 0.f, y1 = 0.f, y2 = 0.f, y3 = 0.f;
#pragma unroll
            for (int s = 0; s < DS; s++) {
                dA *= q;
                float2 bcv = bp[s];
                h[s] = fmaf(dA, h[s], bcv.x * u);
                float t = h[s] * bcv.y;
                if ((s & 3) == 0) y0 += t;
                else if ((s & 3) == 1) y1 += t;
                else if ((s & 3) == 2) y2 += t;
                else y3 += t;
            }
            float y = (y0 + y1) + (y2 + y3);
            float z = *zp;
            float szl = z / (1.f + __expf(-z));
            *ypp = (y + Dv * dv.y) * szl;
            dxp += sdx; bp += sbc; zp += sz; ypp += sy;
        }
    } else {
        for (int i = 0; i < nn; i++) {
            float2 dv = *dxp;
            float u = dv.x * dv.y;
            float y0 = 0.f, y1 = 0.f, y2 = 0.f, y3 = 0.f;
#pragma unroll
            for (int s = 0; s < DS; s++) {
                float2 bcv = bp[s];
                float dA = exp2f(dv.x * a[s]);
                h[s] = fmaf(dA, h[s], bcv.x * u);
                float t = h[s] * bcv.y;
                if ((s & 3) == 0) y0 += t;
                else if ((s & 3) == 1) y1 += t;
                else if ((s & 3) == 2) y2 += t;
                else y3 += t;
            }
            float y = (y0 + y1) + (y2 + y3);
            float z = *zp;
            float szl = z / (1.f + __expf(-z));
            *ypp = (y + Dv * dv.y) * szl;
            dxp += sdx; bp += sbc; zp += sz; ypp += sy;
        }
    }
}

// LayerNorm, float2 lanes
__global__ void ln_kernel(const float* __restrict__ i1,
                          const float* __restrict__ i2,
                          const float* __restrict__ i3,
                          const float* __restrict__ g,
                          const float* __restrict__ bta,
                          float* __restrict__ out)
{
    int row = blockIdx.x * (blockDim.x >> 5) + (threadIdx.x >> 5);
    int lane = threadIdx.x & 31;
    if (row >= TTOK) return;
    const float2* p1 = reinterpret_cast<const float2*>(i1 + (size_t)row * DM);
    const float2* p2 = i2 ? reinterpret_cast<const float2*>(i2 + (size_t)row * DM) : nullptr;
    const float2* p3 = i3 ? reinterpret_cast<const float2*>(i3 + (size_t)row * DM) : nullptr;
    float2 vals[8];
    float s = 0.f, sq = 0.f;
#pragma unroll
    for (int i = 0; i < 8; i++) {
        int j = lane + i * 32;
        float2 v = p1[j];
        if (p2) { float2 w = p2[j]; v.x += w.x; v.y += w.y; }
        if (p3) { float2 w = p3[j]; v.x += w.x; v.y += w.y; }
        vals[i] = v;
        s += v.x + v.y; sq += v.x * v.x + v.y * v.y;
    }
#pragma unroll
    for (int o = 16; o; o >>= 1) {
        s  += __shfl_xor_sync(0xffffffffu, s, o);
        sq += __shfl_xor_sync(0xffffffffu, sq, o);
    }
    float m = s * (1.f / DM);
    float var = sq * (1.f / DM) - m * m;
    float r = rsqrtf(var + 1e-5f);
    const float2* gp = reinterpret_cast<const float2*>(g);
    const float2* bp = reinterpret_cast<const float2*>(bta);
    float2* op = reinterpret_cast<float2*>(out + (size_t)row * DM);
#pragma unroll
    for (int i = 0; i < 8; i++) {
        int j = lane + i * 32;
        float2 gv = gp[j], bv = bp[j];
        op[j] = make_float2((vals[i].x - m) * r * gv.x + bv.x,
                            (vals[i].y - m) * r * gv.y + bv.y);
    }
}

// ================= host orchestration ======================================
template <int ACT>
static void launch_mma(const float* A, int lda, const __half* W, const float* bias,
                       float* C, int ldc, int M, int N, int K,
                       const float* e1 = nullptr, const float* e2 = nullptr,
                       int Z = 1, size_t zsA = 0, size_t zsW = 0,
                       size_t zsC = 0, size_t zsBias = 0)
{
    dim3 grid(CDIV(N, BN), CDIV(M, BM), Z);
    mma_gemm<ACT><<<grid, 256, SMEM_GEMM>>>(A, lda, W, bias, C, ldc,
                                            M, N, K, e1, e2,
                                            zsA, zsW, zsC, zsBias);
}

extern "C" void kernel_launch(void* const* d_in, const int* in_sizes, int n_in,
                              void* d_out, int out_size)
{
    const float* x_enc    = (const float*)d_in[0];
    const float* x_mark   = (const float*)d_in[1];
    const float* emb_w    = (const float*)d_in[4];
    const float* emb_b    = (const float*)d_in[5];
    const float* in_proj  = (const float*)d_in[6];
    const float* conv_w   = (const float*)d_in[7];
    const float* conv_b   = (const float*)d_in[8];
    const float* x_proj   = (const float*)d_in[9];
    const float* dt_w     = (const float*)d_in[10];
    const float* dt_b     = (const float*)d_in[11];
    const float* A_log    = (const float*)d_in[12];
    const float* D_param  = (const float*)d_in[13];
    const float* out_w    = (const float*)d_in[14];
    const float* ffn_w1   = (const float*)d_in[15];
    const float* ffn_b1   = (const float*)d_in[16];
    const float* ffn_w2   = (const float*)d_in[17];
    const float* ffn_b2   = (const float*)d_in[18];
    const float* ln1_g    = (const float*)d_in[19];
    const float* ln1_b    = (const float*)d_in[20];
    const float* ln2_g    = (const float*)d_in[21];
    const float* ln2_b    = (const float*)d_in[22];
    const float* fin_g    = (const float*)d_in[23];
    const float* fin_b    = (const float*)d_in[24];
    const float* gate_w   = (const float*)d_in[25];
    const float* gate_b   = (const float*)d_in[26];
    const float* proj_w   = (const float*)d_in[27];
    const float* proj_b   = (const float*)d_in[28];

    cudaFuncSetAttribute((const void*)mma_gemm<ACT_DUP>,
                         cudaFuncAttributeMaxDynamicSharedMemorySize, SMEM_GEMM);
    cudaFuncSetAttribute((const void*)mma_gemm<ACT_NONE>,
                         cudaFuncAttributeMaxDynamicSharedMemorySize, SMEM_GEMM);
    cudaFuncSetAttribute((const void*)mma_gemm<ACT_DELTABC>,
                         cudaFuncAttributeMaxDynamicSharedMemorySize, SMEM_GEMM);
    cudaFuncSetAttribute((const void*)mma_gemm<ACT_RELU>,
                         cudaFuncAttributeMaxDynamicSharedMemorySize, SMEM_GEMM);
    cudaFuncSetAttribute((const void*)mma_gemm<ACT_GATE>,
                         cudaFuncAttributeMaxDynamicSharedMemorySize, SMEM_GEMM);
    cudaFuncSetAttribute((const void*)mma_gemm<ACT_FINAL>,
                         cudaFuncAttributeMaxDynamicSharedMemorySize, SMEM_GEMM);

    float* S = nullptr;
    cudaGetSymbolAddress((void**)&S, g_scratch);

    float* tok   = S + OFF_TOK;
    float* enc   = S + OFF_ENC;
    float* raw   = S + OFF_RAW;
    float* xzB   = S + OFF_XZB;
    float* xcb[2] = { S + OFF_XC0,  S + OFF_XC1 };
    float* dx    = S + OFF_DX;
    float* bcb   = S + OFF_BC;
    float* yp    = S + OFF_YP;
    float* mo    = S + OFF_MO;
    float* t1    = S + OFF_T1;
    float* t2    = S + OFF_T2;
    float* t3    = S + OFF_T3;
    __half* wh   = (__half*)(S + OFF_WH);
    __half* wch  = (__half*)(S + OFF_WCH);
    float* means = S + OFF_MEAN;
    float* stds  = S + OFF_STD;
    float* Pbuf  = S + OFF_P;
    float* Hlbuf = S + OFF_HL;
    float* Hibuf = S + OFF_HI;

    __half* emb_h  = wh;
    __half* inp_h  = emb_h + N_EMB;
    __half* out_h  = inp_h + N_INP;    // concatenated [l][512][1024]
    __half* f1_h   = out_h + N_OUT;
    __half* f2_h   = f1_h + N_F1;
    __half* gw_h   = f2_h + N_F2;
    __half* pw_h   = gw_h + N_GW;

    wconv_kernel<<<CDIV(N_WALL, 256), 256>>>(emb_w, in_proj, out_w, ffn_w1,
                                             ffn_w2, gate_w, proj_w, wh);
    wcomb_kernel<<<CDIV(N_WC, 256), 256>>>(dt_w, x_proj, wch);
    stats_tok_kernel<<<CDIV(BATCH * LTOK, 256), 256>>>(x_enc, x_mark,
                                                       means, stds, tok);

    // embedding GEMM -> enc (+ duplicate into raw)
    launch_mma<ACT_DUP>(tok, SEQ, emb_h, emb_b, enc, DM, TTOK, DM, SEQ,
                        nullptr, raw);

    for (int l = 0; l < NL; l++) {
        // merged fwd+rev in_proj: N=2048
        launch_mma<ACT_NONE>(enc, DM, inp_h + (size_t)l * 2 * 2 * DM * DM,
                             nullptr, xzB, 4 * DM, TTOK, 4 * DM, DM);
        conv_silu_kernel<<<CDIV(2 * TTOK * 256, 256), 256>>>(
            xzB, conv_w + (size_t)l * 2 * DM * 2, conv_b + (size_t)l * 2 * DM,
            xcb[0], xcb[1], dx);

        // fused delta(softplus)+B+C GEMM, both dirs (z=2)
        launch_mma<ACT_DELTABC>(xcb[0], DM, wch + (size_t)l * 2 * 544 * 512,
                                dt_b + (size_t)l * 2 * DM, dx, 2048,
                                TTOK, 544, DM, bcb, nullptr,
                                2, (size_t)TTOK * DM, (size_t)544 * 512,
                                1024, DM);

        // chunked scan (three-kernel structure — proven fastest)
        scan_p1<<<NWARP / 8, 256>>>(dx, bcb,
                                    A_log + (size_t)l * 2 * DM * DS,
                                    Pbuf, Hlbuf);
        scan_comb<<<CDIV(2 * BATCH * DM * 16, 256), 256>>>(Pbuf, Hlbuf, Hibuf);
        scan_p2<<<NWARP / 8, 256>>>(dx, bcb, xzB,
                                    A_log + (size_t)l * 2 * DM * DS,
                                    D_param + (size_t)l * 2 * DM,
                                    Hibuf, yp);

        // merged out projection: mo = yp_fwd@W0^T + yp_rev@W1^T (K=1024)
        launch_mma<ACT_NONE>(yp, 1024, out_h + (size_t)l * 512 * 1024,
                             nullptr, mo, DM, TTOK, DM, 1024);

        ln_kernel<<<CDIV(TTOK, 8), 256>>>(enc, mo, nullptr,
                                          ln1_g + l * DM, ln1_b + l * DM, t1);
        launch_mma<ACT_RELU>(t1, DM, f1_h + (size_t)l * DFF * DM,
                             ffn_b1 + l * DFF, t2, DFF, TTOK, DFF, DM);
        launch_mma<ACT_NONE>(t2, DFF, f2_h + (size_t)l * DM * DFF,
                             ffn_b2 + l * DM, t3, DM, TTOK, DM, DFF);
        ln_kernel<<<CDIV(TTOK, 8), 256>>>(t1, t3, nullptr,
                                          ln2_g + l * DM, ln2_b + l * DM, enc);
    }

    ln_kernel<<<CDIV(TTOK, 8), 256>>>(enc, nullptr, nullptr, fin_g, fin_b, t2);
    launch_mma<ACT_GATE>(raw, DM, gw_h, gate_b, t1, DM, TTOK, DM, DM,
                         t2, raw);
    // final projection fused with transpose + de-instance-norm -> d_out
    launch_mma<ACT_FINAL>(t1, DM, pw_h, proj_b, (float*)d_out, 0,
                          TTOK, PRED, DM, means, stds);
}